// round 8
// baseline (speedup 1.0000x reference)
#include <cuda_runtime.h>
#include <cstdint>

#define SEQ 32
#define EDIM 256
#define HDIM 256
#define GDIM 1024
#define NTHREADS 256

#define XSP 260                       // padded x-tile row stride (floats)

// ---------------- device scratch ----------------
// fragment-packed tf32 weights: [g8][kb32][nf16][lane32] uint2 (slice-contiguous per g)
__device__ __align__(16) uint2 g_wih_pk[8*32*16*32];
__device__ __align__(16) uint2 g_whh_pk[8*32*16*32];
__device__ float g_bperm[GDIM];
// xg in fragment-native layout: block[(rowtile*32+s)*8+g] of 4096 floats
__device__ __align__(16) float g_xg[(size_t)128*32*8*4096];
// h exchange, k-major: [parity2][tile128][unit256][row32]
__device__ __align__(16) float g_hex[2*128*256*32];
// arrival counters [rgrp16][subtile8][step31] + exit latch
__device__ unsigned g_cnt[16*8*31];
__device__ unsigned g_done[16];

__device__ __forceinline__ float tf32_round_f(float x) {
    float r; asm("cvt.rna.tf32.f32 %0, %1;" : "=f"(r) : "f"(x)); return r;
}
__device__ __forceinline__ uint32_t tf32_round_u(float x) {
    uint32_t r; asm("cvt.rna.tf32.f32 %0, %1;" : "=r"(r) : "f"(x)); return r;
}
__device__ __forceinline__ uint32_t ld_acq(const unsigned* p) {
    uint32_t v; asm volatile("ld.acquire.gpu.global.u32 %0, [%1];" : "=r"(v) : "l"(p) : "memory");
    return v;
}

#define MMA_TF32(d, a, b0, b1)                                              \
    asm volatile("mma.sync.aligned.m16n8k8.row.col.f32.tf32.tf32.f32 "      \
                 "{%0,%1,%2,%3}, {%4,%5,%6,%7}, {%8,%9}, {%0,%1,%2,%3};"    \
                 : "+f"((d)[0]), "+f"((d)[1]), "+f"((d)[2]), "+f"((d)[3])   \
                 : "r"((a)[0]), "r"((a)[1]), "r"((a)[2]), "r"((a)[3]),      \
                   "r"(b0), "r"(b1))

__device__ __forceinline__ float sigmoidf_(float x) {
    return 1.0f / (1.0f + __expf(-x));
}

// =================== prep: permute + tf32 + fragment-pack ===================
__global__ void prep_kernel(const float* __restrict__ wih,
                            const float* __restrict__ whh,
                            const float* __restrict__ bih,
                            const float* __restrict__ bhh) {
    int i = blockIdx.x * blockDim.x + threadIdx.x;   // 0..131071
    if (i >= 8*32*16*32) return;
    int lane = i & 31;
    int nf   = (i >> 5) & 15;
    int kb   = (i >> 9) & 31;
    int g    = (i >> 14) & 7;
    int grp  = lane >> 2;
    int tg   = lane & 3;

    int colperm = g*128 + nf*8 + grp;
    int unit = colperm >> 2, gate = colperm & 3;
    int orow = gate*256 + unit;
    int kk   = kb*8 + tg;

    uint2 v;
    v.x = tf32_round_u(wih[orow*256 + kk]);
    v.y = tf32_round_u(wih[orow*256 + kk + 4]);
    g_wih_pk[i] = v;
    v.x = tf32_round_u(whh[orow*256 + kk]);
    v.y = tf32_round_u(whh[orow*256 + kk + 4]);
    g_whh_pk[i] = v;

    if (i < GDIM) {
        int u2 = i >> 2, g2 = i & 3;
        g_bperm[i] = bih[g2*256 + u2] + bhh[g2*256 + u2];
    }
}

// =================== kernel A: xg = x @ W_ih^T + b (weight-stationary) ===================
// grid 128 = g(8) x rg(16). smem: Ws slice 128KB + x stage (2 tiles) 66.5KB
#define A_WS_BYTES 131072
#define A_XS_OFF   (A_WS_BYTES/4)       // float index of Xs in smem
#define SMEM_A_BYTES (A_WS_BYTES + 2*32*XSP*4)

__global__ __launch_bounds__(NTHREADS, 1)
void xg_gemm_kernel(const float* __restrict__ x) {
    extern __shared__ float sm[];
    uint2* Ws = (uint2*)sm;                 // [kb32][nf16][lane32]
    float* Xs = sm + A_XS_OFF;              // [2 tiles][32][XSP]

    const int tid  = threadIdx.x;
    const int lane = tid & 31;
    const int w    = tid >> 5;
    const int grp  = lane >> 2;
    const int tg   = lane & 3;
    const int g    = blockIdx.x & 7;
    const int rg   = blockIdx.x >> 3;
    const int t    = w >> 2;        // tile within pair
    const int cg   = w & 3;         // col group (32 cols)

    // load W slice to smem (128KB, coalesced)
    {
        const uint4* src = (const uint4*)(g_wih_pk + (size_t)g*16384);
        uint4* dst = (uint4*)Ws;
        #pragma unroll
        for (int j = tid; j < 8192; j += NTHREADS) dst[j] = src[j];
    }

    float4 rbuf[16];
    // preload iteration 0
    {
        int rt = rg*8, s0 = 0;
        #pragma unroll
        for (int j = 0; j < 16; ++j) {
            int t2 = j >> 3, jj = j & 7;
            int fi = tid + jj*256, r = fi >> 6, cq = fi & 63;
            rbuf[j] = *(const float4*)(x + (((size_t)(rt*32 + r))*32 + (s0 + t2))*256 + cq*4);
        }
    }

    for (int it = 0; it < 128; ++it) {
        const int rt = rg*8 + (it >> 4);
        const int s0 = (it & 15)*2;

        __syncthreads();
        // STS staged tiles (tf32-rounded)
        #pragma unroll
        for (int j = 0; j < 16; ++j) {
            int t2 = j >> 3, jj = j & 7;
            int fi = tid + jj*256, r = fi >> 6, cq = fi & 63;
            float* dp = &Xs[(t2*32 + r)*XSP + cq*4];
            dp[0] = tf32_round_f(rbuf[j].x);
            dp[1] = tf32_round_f(rbuf[j].y);
            dp[2] = tf32_round_f(rbuf[j].z);
            dp[3] = tf32_round_f(rbuf[j].w);
        }
        __syncthreads();

        // preload next iteration while computing
        if (it + 1 < 128) {
            int rt2 = rg*8 + ((it + 1) >> 4);
            int s02 = ((it + 1) & 15)*2;
            #pragma unroll
            for (int j = 0; j < 16; ++j) {
                int t2 = j >> 3, jj = j & 7;
                int fi = tid + jj*256, r = fi >> 6, cq = fi & 63;
                rbuf[j] = *(const float4*)(x + (((size_t)(rt2*32 + r))*32 + (s02 + t2))*256 + cq*4);
            }
        }

        // compute: warp -> tile t, cols cg*32..+32
        float d[2][4][4];
        #pragma unroll
        for (int nf = 0; nf < 4; ++nf) {
            int col = g*128 + (cg*4 + nf)*8 + 2*tg;
            float b0 = g_bperm[col], b1 = g_bperm[col + 1];
            d[0][nf][0] = b0; d[0][nf][1] = b1; d[0][nf][2] = b0; d[0][nf][3] = b1;
            d[1][nf][0] = b0; d[1][nf][1] = b1; d[1][nf][2] = b0; d[1][nf][3] = b1;
        }
        const uint32_t* A = (const uint32_t*)(Xs + t*32*XSP);
        #pragma unroll 4
        for (int kb = 0; kb < 32; ++kb) {
            const int k8 = kb*8;
            uint32_t a[2][4];
            #pragma unroll
            for (int mh = 0; mh < 2; ++mh) {
                int r0 = mh*16 + grp;
                a[mh][0] = A[r0*XSP + k8 + tg];
                a[mh][1] = A[(r0+8)*XSP + k8 + tg];
                a[mh][2] = A[r0*XSP + k8 + 4 + tg];
                a[mh][3] = A[(r0+8)*XSP + k8 + 4 + tg];
            }
            #pragma unroll
            for (int nf = 0; nf < 4; ++nf) {
                uint2 b = Ws[(kb*16 + cg*4 + nf)*32 + lane];
                MMA_TF32(d[0][nf], a[0], b.x, b.y);
                MMA_TF32(d[1][nf], a[1], b.x, b.y);
            }
        }
        // store fragments to g_xg (lane-major, coalesced)
        {
            float2* xp = (float2*)(g_xg + (((size_t)(rt*32 + s0 + t)*8 + g)*4096));
            #pragma unroll
            for (int mh = 0; mh < 2; ++mh)
                #pragma unroll
                for (int nf = 0; nf < 4; ++nf) {
                    int nfg = mh*16 + cg*4 + nf;
                    float2 v0 = make_float2(d[mh][nf][0], d[mh][nf][1]);
                    float2 v1 = make_float2(d[mh][nf][2], d[mh][nf][3]);
                    xp[(nfg*2 + 0)*32 + lane] = v0;
                    xp[(nfg*2 + 1)*32 + lane] = v1;
                }
        }
    }
}

// =================== kernel B: recurrence (weight-stationary, h via L2) ===================
#define SMEM_B_BYTES 131072

__global__ __launch_bounds__(NTHREADS, 1)
void lstm_rec_kernel(float* __restrict__ out) {
    extern __shared__ float sm[];
    uint2* Ws = (uint2*)sm;                 // [kb32][nf16][lane32]

    const int tid  = threadIdx.x;
    const int lane = tid & 31;
    const int w    = tid >> 5;              // subtile 0..7
    const int grp  = lane >> 2;
    const int tg   = lane & 3;
    const int tgl  = tg & 1;
    const int tgh  = tg >> 1;
    const int g    = blockIdx.x & 7;
    const int rg   = blockIdx.x >> 3;
    const int tile = rg*8 + w;              // global row tile 0..127

    // load W_hh slice to smem
    {
        const uint4* src = (const uint4*)(g_whh_pk + (size_t)g*16384);
        uint4* dst = (uint4*)Ws;
        #pragma unroll
        for (int j = tid; j < 8192; j += NTHREADS) dst[j] = src[j];
    }
    __syncthreads();

    float cst[2][16];
    #pragma unroll
    for (int a = 0; a < 2; ++a)
        #pragma unroll
        for (int b = 0; b < 16; ++b) cst[a][b] = 0.0f;

    for (int s = 0; s < SEQ; ++s) {
        // wait for all 8 col-CTAs' h of step s-1 for this tile
        if (s > 0) {
            const unsigned* cp = &g_cnt[(rg*8 + w)*31 + (s - 1)];
            if (lane == 0) {
                while (ld_acq(cp) < 8u) { __nanosleep(64); }
            }
            __syncwarp();
        }

        // init accumulators from xg (coalesced fragment loads)
        float d[2][16][4];
        {
            const float2* xp = (const float2*)(g_xg + (((size_t)(tile*32 + s)*8 + g)*4096));
            #pragma unroll
            for (int mh = 0; mh < 2; ++mh)
                #pragma unroll
                for (int nf = 0; nf < 16; ++nf) {
                    int nfg = mh*16 + nf;
                    float2 v0 = xp[(nfg*2 + 0)*32 + lane];
                    float2 v1 = xp[(nfg*2 + 1)*32 + lane];
                    d[mh][nf][0] = v0.x; d[mh][nf][1] = v0.y;
                    d[mh][nf][2] = v1.x; d[mh][nf][3] = v1.y;
                }
        }

        if (s > 0) {
            const int pr = (s & 1) ^ 1;
            const uint32_t* A = (const uint32_t*)(g_hex + ((size_t)(pr*128 + tile)*256)*32);
            #pragma unroll 4
            for (int kb = 0; kb < 32; ++kb) {
                const int k8 = kb*8;
                uint32_t a[2][4];
                #pragma unroll
                for (int mh = 0; mh < 2; ++mh) {
                    int r0 = mh*16 + grp;
                    a[mh][0] = A[(k8 + tg)*32 + r0];
                    a[mh][1] = A[(k8 + tg)*32 + r0 + 8];
                    a[mh][2] = A[(k8 + 4 + tg)*32 + r0];
                    a[mh][3] = A[(k8 + 4 + tg)*32 + r0 + 8];
                }
                #pragma unroll
                for (int nf = 0; nf < 16; ++nf) {
                    uint2 b = Ws[(kb*16 + nf)*32 + lane];
                    MMA_TF32(d[0][nf], a[0], b.x, b.y);
                    MMA_TF32(d[1][nf], a[1], b.x, b.y);
                }
            }
        }

        // activation in registers
        const int pw = s & 1;
        float* hexw = g_hex + ((size_t)(pw*128 + tile)*256)*32;
        #pragma unroll
        for (int mh = 0; mh < 2; ++mh) {
            #pragma unroll
            for (int nf = 0; nf < 16; ++nf) {
                float c0 = d[mh][nf][0], c1 = d[mh][nf][1];
                float c2 = d[mh][nf][2], c3 = d[mh][nf][3];
                float x0 = __shfl_xor_sync(0xffffffffu, tgl ? c0 : c2, 1);
                float x1 = __shfl_xor_sync(0xffffffffu, tgl ? c1 : c3, 1);
                float gi = tgl ? x0 : c0;
                float gf = tgl ? x1 : c1;
                float gg = tgl ? c2 : x0;
                float go = tgl ? c3 : x1;
                int row = grp + 8*tgl + 16*mh;       // 0..31 within tile
                int ul  = 2*nf + tgh;                // 0..31 within col slice
                float cv = sigmoidf_(gf) * cst[mh][nf]
                         + sigmoidf_(gi) * tanhf(gg);
                cst[mh][nf] = cv;
                float h = sigmoidf_(go) * tanhf(cv);
                if (s < SEQ - 1) {
                    hexw[(size_t)(g*32 + ul)*32 + row] = tf32_round_f(h);
                } else {
                    out[(size_t)(rg*256 + w*32 + row)*256 + g*32 + ul] = h;
                }
            }
        }

        // signal h of step s available
        if (s < SEQ - 1) {
            __syncwarp();
            __threadfence();
            if (lane == 0) atomicAdd(&g_cnt[(rg*8 + w)*31 + s], 1u);
        }
    }

    // cleanup: last CTA of this row-group zeroes its counters (graph-replay safe)
    __syncthreads();
    if (tid == 0) {
        unsigned old = atomicAdd(&g_done[rg], 1u);
        if (old == 7u) {
            for (int k = 0; k < 8*31; ++k) g_cnt[rg*248 + k] = 0u;
            __threadfence();
            atomicExch(&g_done[rg], 0u);
        }
    }
}

extern "C" void kernel_launch(void* const* d_in, const int* in_sizes, int n_in,
                              void* d_out, int out_size) {
    const float* x   = (const float*)d_in[0];
    const float* wih = (const float*)d_in[1];
    const float* whh = (const float*)d_in[2];
    const float* bih = (const float*)d_in[3];
    const float* bhh = (const float*)d_in[4];
    float* out = (float*)d_out;

    cudaFuncSetAttribute(xg_gemm_kernel,
                         cudaFuncAttributeMaxDynamicSharedMemorySize, SMEM_A_BYTES);
    cudaFuncSetAttribute(lstm_rec_kernel,
                         cudaFuncAttributeMaxDynamicSharedMemorySize, SMEM_B_BYTES);

    prep_kernel<<<512, 256>>>(wih, whh, bih, bhh);
    xg_gemm_kernel<<<128, NTHREADS, SMEM_A_BYTES>>>(x);
    lstm_rec_kernel<<<128, NTHREADS, SMEM_B_BYTES>>>(out);
}